// round 12
// baseline (speedup 1.0000x reference)
#include <cuda_runtime.h>
#include <cuda_fp16.h>

#define D 128
#define NMAX 50048               // covers MLP grid padding (1564 * 32)
#define PAD 64                   // bucket slots per dst
#define HASH_SIZE (1u << 21)
#define OVF_MAX 4096

// ---------------- device-global scratch (no allocations allowed) ------------
__device__ unsigned long long g_hash[HASH_SIZE];      // gen-tagged, never cleared
__device__ unsigned int g_gen;
__device__ float g_h[(size_t)NMAX * D];               // 25.6 MB
__device__ float g_h1[(size_t)NMAX * D];              // 25.6 MB (layer-1 output)
__device__ uint2 g_nf16[(size_t)NMAX * D / 4];        // 12.8 MB fp16 mirror
__device__ int g_cnt[NMAX];
__device__ int g_bucket[(size_t)NMAX * PAD];          // 12.8 MB
__device__ int g_ovf[OVF_MAX * 2];
__device__ int g_ovf_cnt;
__device__ int g_idx64;

// ---------------- packed f32x2 helpers (Blackwell FFMA2) --------------------
__device__ __forceinline__ unsigned long long ffma2(unsigned long long a,
                                                    unsigned long long b,
                                                    unsigned long long c) {
    unsigned long long d;
    asm("fma.rn.f32x2 %0, %1, %2, %3;" : "=l"(d) : "l"(a), "l"(b), "l"(c));
    return d;
}
__device__ __forceinline__ unsigned long long pack2(float lo, float hi) {
    unsigned long long r;
    asm("mov.b64 %0, {%1, %2};" : "=l"(r) : "f"(lo), "f"(hi));
    return r;
}
__device__ __forceinline__ void unpack2(unsigned long long v, float& lo, float& hi) {
    asm("mov.b64 {%0, %1}, %2;" : "=f"(lo), "=f"(hi) : "l"(v));
}
__device__ __forceinline__ __half2 h2_from_u32(unsigned int u) {
    return reinterpret_cast<const __half2&>(u);
}
__device__ __forceinline__ unsigned int u32_from_h2(__half2 h) {
    return reinterpret_cast<const unsigned int&>(h);
}

// ---- phase 0: zero counts, build fp16 mirror, detect index dtype -----------
__global__ void __launch_bounds__(256)
k_setup(const float4* __restrict__ nf, const unsigned int* __restrict__ src,
        int n4) {
    int i = blockIdx.x * blockDim.x + threadIdx.x;
    if (i < n4) {
        float4 a = nf[i];
        uint2 o;
        o.x = u32_from_h2(__float22half2_rn(make_float2(a.x, a.y)));
        o.y = u32_from_h2(__float22half2_rn(make_float2(a.z, a.w)));
        g_nf16[i] = o;
    }
    if (i < NMAX) g_cnt[i] = 0;
    if (i == 0) {
        g_ovf_cnt = 0;
        g_gen = g_gen + 1;
        int is64 = 1;
#pragma unroll
        for (int k = 0; k < 8; k++)
            if (src[2 * k + 1] != 0u) is64 = 0;
        g_idx64 = is64;
    }
}

// ---- phase 1: fused dedup + bucket fill (thread per edge) ------------------
__global__ void __launch_bounds__(256)
k_dedup_fill(const void* __restrict__ srcp, const void* __restrict__ dstp,
             int nE) {
    int e = blockIdx.x * blockDim.x + threadIdx.x;
    if (e >= nE) return;
    int s, d;
    if (g_idx64) {
        s = (int)((const long long*)srcp)[e];
        d = (int)((const long long*)dstp)[e];
    } else {
        s = ((const int*)srcp)[e];
        d = ((const int*)dstp)[e];
    }

    unsigned int gen = g_gen;
    unsigned int key = ((unsigned)s << 16) | (unsigned)d;
    unsigned long long want = ((unsigned long long)gen << 32) | key;
    unsigned int slot = (key * 0x9E3779B1u) >> (32 - 21);

    for (;;) {
        unsigned long long cur;
        asm volatile("ld.global.cg.u64 %0, [%1];"
                     : "=l"(cur) : "l"(&g_hash[slot]));
        if (cur == want) return;
        if ((unsigned int)(cur >> 32) != gen) {
            unsigned long long prev = atomicCAS(&g_hash[slot], cur, want);
            if (prev == cur) break;
            if (prev == want) return;
            if ((unsigned int)(prev >> 32) != gen) continue;
        }
        slot = (slot + 1) & (HASH_SIZE - 1);
    }
    int pos = atomicAdd(&g_cnt[d], 1);
    if (pos < PAD) {
        g_bucket[(size_t)d * PAD + pos] = s;
    } else {
        int o = atomicAdd(&g_ovf_cnt, 1);
        if (o < OVF_MAX) { g_ovf[2 * o] = s; g_ovf[2 * o + 1] = d; }
    }
}

// ---- phase 2: warp-per-dst fp16 gather-sum + (1+alpha)*x + fused overflow --
__global__ void __launch_bounds__(256)
k_agg(const float* __restrict__ nfeats, const float* __restrict__ alpha,
      int nrows) {
    int w = (int)((blockIdx.x * 256u + threadIdx.x) >> 5);
    int lane = threadIdx.x & 31;
    if (w >= nrows) return;

    const float4* nf4 = (const float4*)nfeats;
    float sc = 1.0f + alpha[0];

    float4 a = nf4[(size_t)w * 32 + lane];
    float4 acc = make_float4(a.x * sc, a.y * sc, a.z * sc, a.w * sc);

    int cnt = g_cnt[w];
    if (cnt > PAD) cnt = PAD;
    const int* bk = &g_bucket[(size_t)w * PAD];

#define ACC_H8(u)                                                         \
    do {                                                                  \
        float2 f0 = __half22float2(h2_from_u32((u).x));                   \
        float2 f1 = __half22float2(h2_from_u32((u).y));                   \
        acc.x += f0.x; acc.y += f0.y; acc.z += f1.x; acc.w += f1.y;       \
    } while (0)

    int j = 0;
    for (; j + 4 <= cnt; j += 4) {
        int s0 = bk[j], s1 = bk[j + 1], s2 = bk[j + 2], s3 = bk[j + 3];
        uint2 v0 = g_nf16[(size_t)s0 * 32 + lane];
        uint2 v1 = g_nf16[(size_t)s1 * 32 + lane];
        uint2 v2 = g_nf16[(size_t)s2 * 32 + lane];
        uint2 v3 = g_nf16[(size_t)s3 * 32 + lane];
        ACC_H8(v0); ACC_H8(v1); ACC_H8(v2); ACC_H8(v3);
    }
    for (; j < cnt; j++) {
        uint2 v0 = g_nf16[(size_t)bk[j] * 32 + lane];
        ACC_H8(v0);
    }
#undef ACC_H8

    int novf = g_ovf_cnt;
    if (novf > 0) {
        if (novf > OVF_MAX) novf = OVF_MAX;
        for (int k = 0; k < novf; k++) {
            if (g_ovf[2 * k + 1] == w) {
                int s = g_ovf[2 * k];
                float4 u = nf4[(size_t)s * 32 + lane];
                acc.x += u.x; acc.y += u.y; acc.z += u.z; acc.w += u.w;
            }
        }
    }

    ((float4*)g_h)[(size_t)w * 32 + lane] = acc;
}

// ---- phase 3: MLP layer, 32-row blocks, 4 rows x 4 cols per thread ---------
// smem: W half [64][128] (32KB) + H half [32][64] (8KB) = 40.5KB.
// __launch_bounds__(256, 4) caps regs at 64 -> 4 blocks/SM = 32 warps.
template <bool RELU, bool GUARD>
__device__ __forceinline__ void
mlp_layer_body(const float* __restrict__ Wg, const float* __restrict__ bg,
               const float* __restrict__ gin, float* __restrict__ gout,
               int nrows) {
    extern __shared__ float smem[];
    float* sW = smem;                  // 8192 floats (64 k-rows x 128 cols)
    float* sH = smem + 8192;           // 2048 floats (32 rows x 64 k)

    int tid = threadIdx.x;
    int x = tid & 31;                  // col group: cols [4x, 4x+4)
    int y = tid >> 5;                  // row group: rows [4y, 4y+4)
    int row0 = blockIdx.x * 32;

    unsigned long long a01[4], a23[4];
    {
        float4 bv = *(const float4*)(bg + x * 4);
        unsigned long long i01 = pack2(bv.x, bv.y), i23 = pack2(bv.z, bv.w);
#pragma unroll
        for (int i = 0; i < 4; i++) { a01[i] = i01; a23[i] = i23; }
    }

#pragma unroll
    for (int phase = 0; phase < 2; phase++) {
        if (phase) __syncthreads();

        // fill W half: k rows [phase*64, phase*64+64), all 128 cols
        {
            const float4* wg4 = (const float4*)(Wg + phase * 64 * D);
            for (int i = tid; i < 2048; i += 256) ((float4*)sW)[i] = wg4[i];
        }
        // fill H half: 32 rows x k cols [phase*64, phase*64+64)
        for (int i = tid; i < 512; i += 256) {
            int r = i >> 4, c4 = i & 15;
            ((float4*)sH)[i] =
                *(const float4*)(gin + (size_t)(row0 + r) * D + phase * 64 + c4 * 4);
        }
        __syncthreads();

        const float* hrow = sH + y * 4 * 64;
#pragma unroll 4
        for (int k0 = 0; k0 < 64; k0 += 4) {
            float4 h4[4];
#pragma unroll
            for (int i = 0; i < 4; i++)
                h4[i] = *(const float4*)(hrow + i * 64 + k0);
#pragma unroll
            for (int kk = 0; kk < 4; kk++) {
                ulonglong2 wv =
                    *(const ulonglong2*)(sW + (k0 + kk) * D + x * 4);
#pragma unroll
                for (int i = 0; i < 4; i++) {
                    float hk = (&h4[i].x)[kk];
                    unsigned long long h2 = pack2(hk, hk);
                    a01[i] = ffma2(h2, wv.x, a01[i]);
                    a23[i] = ffma2(h2, wv.y, a23[i]);
                }
            }
        }
    }

#pragma unroll
    for (int i = 0; i < 4; i++) {
        int gr = row0 + y * 4 + i;
        if (!GUARD || gr < nrows) {
            float f0, f1, f2, f3;
            unpack2(a01[i], f0, f1); unpack2(a23[i], f2, f3);
            if (RELU) {
                f0 = fmaxf(f0, 0.f); f1 = fmaxf(f1, 0.f);
                f2 = fmaxf(f2, 0.f); f3 = fmaxf(f3, 0.f);
            }
            *(float4*)(gout + (size_t)gr * D + x * 4) =
                make_float4(f0, f1, f2, f3);
        }
    }
}

__global__ void __launch_bounds__(256, 4)
k_mlp1(const float* __restrict__ W1, const float* __restrict__ b1, int nrows) {
    mlp_layer_body<true, false>(W1, b1, g_h, g_h1, nrows);
}

__global__ void __launch_bounds__(256, 4)
k_mlp2(const float* __restrict__ W2, const float* __restrict__ b2,
       float* __restrict__ out, int nrows) {
    mlp_layer_body<false, true>(W2, b2, g_h1, out, nrows);
}

// ---------------- launch ----------------------------------------------------
#define MLP_SMEM (10240 * 4)     // 40960 bytes: W half 32KB + H half 8KB

extern "C" void kernel_launch(void* const* d_in, const int* in_sizes, int n_in,
                              void* d_out, int out_size) {
    const float* nfeats = (const float*)d_in[0];
    const void*  src    = d_in[1];
    const void*  dst    = d_in[2];
    const float* W1     = (const float*)d_in[3];
    const float* b1     = (const float*)d_in[4];
    const float* W2     = (const float*)d_in[5];
    const float* b2     = (const float*)d_in[6];
    const float* alpha  = (const float*)d_in[7];
    float* out = (float*)d_out;

    int nE    = in_sizes[1];
    int nrows = in_sizes[0] / D;
    int n4    = nrows * (D / 4);

    int setup_items = n4 > NMAX ? n4 : NMAX;
    k_setup<<<(setup_items + 255) / 256, 256>>>(
        (const float4*)nfeats, (const unsigned int*)src, n4);
    k_dedup_fill<<<(nE + 255) / 256, 256>>>(src, dst, nE);
    k_agg<<<(nrows + 7) / 8, 256>>>(nfeats, alpha, nrows);

    cudaFuncSetAttribute(k_mlp1, cudaFuncAttributeMaxDynamicSharedMemorySize,
                         MLP_SMEM);
    cudaFuncSetAttribute(k_mlp2, cudaFuncAttributeMaxDynamicSharedMemorySize,
                         MLP_SMEM);
    int nblk = (nrows + 31) / 32;
    k_mlp1<<<nblk, 256, MLP_SMEM>>>(W1, b1, nrows);
    k_mlp2<<<nblk, 256, MLP_SMEM>>>(W2, b2, out, nrows);
}